// round 1
// baseline (speedup 1.0000x reference)
#include <cuda_runtime.h>

#define B_  8
#define H_  224
#define W_  224
#define C_  192
#define KS  7
#define QT  16       // q positions per block
#define NQ  2        // q per thread
#define RH  56       // output rows per block
#define CPB 64       // channels per block
#define PAIRS 32     // channel pairs (threadIdx.x)
#define QTH  8       // q-thread groups (threadIdx.y)
#define NTHREADS 256
#define SROW (QT + 6)              // 22 staged columns per row
#define STAGE_V4 (SROW * (CPB/4))  // 352 float4 per row stage

typedef unsigned long long u64;

__device__ __forceinline__ void fma2(u64 &d, u64 a, u64 b) {
    // packed f32x2 FMA: 2 fp32 FMAs in one instruction (Blackwell)
    asm("fma.rn.f32x2 %0, %1, %2, %0;" : "+l"(d) : "l"(a), "l"(b));
}
__device__ __forceinline__ u64 pack2(float lo, float hi) {
    return (u64)__float_as_uint(lo) | ((u64)__float_as_uint(hi) << 32);
}

__global__ void __launch_bounds__(NTHREADS, 1)
dwconv_circ_kernel(const float* __restrict__ x, const float* __restrict__ kern,
                   float* __restrict__ out)
{
    __shared__ float sbuf[2][SROW][CPB];   // 11,264 B double-buffered row stage

    const int tx  = threadIdx.x;           // channel pair 0..31
    const int ty  = threadIdx.y;           // q group 0..7
    const int tid = ty * PAIRS + tx;

    const int wt = blockIdx.x;              // 0..13
    const int ht = blockIdx.y;              // 0..3
    const int bz = blockIdx.z;              // 0..23
    const int b  = bz / 3;
    const int g  = bz % 3;

    const int qbase = wt * QT;
    const int p0    = ht * RH;
    const int cbase = g * CPB;
    const int c0    = cbase + 2 * tx;

    // ---- kernel taps for this channel pair -> registers (49 x f32x2) ----
    u64 kreg[KS * KS];
    #pragma unroll
    for (int t = 0; t < KS * KS; ++t)
        kreg[t] = pack2(kern[c0 * 49 + t], kern[(c0 + 1) * 49 + t]);

    // ---- staging address plan (row-invariant column offsets) ----
    const int s0 = tid / (CPB / 4), v0 = tid % (CPB / 4);
    const int idx1 = tid + NTHREADS;
    const bool has1 = idx1 < STAGE_V4;
    const int s1 = idx1 / (CPB / 4), v1 = idx1 % (CPB / 4);
    int qg0 = qbase - 3 + s0; qg0 += (qg0 < 0) ? W_ : 0; qg0 -= (qg0 >= W_) ? W_ : 0;
    int qg1 = qbase - 3 + s1; qg1 += (qg1 < 0) ? W_ : 0; qg1 -= (qg1 >= W_) ? W_ : 0;
    const int colOff0 = qg0 * C_ + cbase + v0 * 4;
    const int colOff1 = qg1 * C_ + cbase + v1 * 4;

    const int r0 = p0 - 3;
    const int r1 = p0 + RH + 3;   // exclusive

    // ---- prologue: stage first input row into buffer 0 ----
    {
        int rr = r0; rr += (rr < 0) ? H_ : 0;
        const int rowBase = (b * H_ + rr) * W_ * C_;
        *(float4*)&sbuf[0][s0][v0 * 4] = *(const float4*)(x + rowBase + colOff0);
        if (has1)
            *(float4*)&sbuf[0][s1][v1 * 4] = *(const float4*)(x + rowBase + colOff1);
    }
    __syncthreads();

    // rolling ring: acc[m] holds partial output row p = r - 3 + m
    u64 acc[7][NQ];
    #pragma unroll
    for (int m = 0; m < 7; ++m) { acc[m][0] = 0ULL; acc[m][1] = 0ULL; }

    const int qOut = qbase + ty * NQ;

    for (int r = r0; r < r1; ++r) {
        const int bi = (r - r0) & 1;

        // prefetch next input row into registers (hidden under FMAs)
        float4 pre0, pre1;
        const bool doPre = (r + 1 < r1);
        if (doPre) {
            int rn = r + 1;
            rn += (rn < 0) ? H_ : 0;
            rn -= (rn >= H_) ? H_ : 0;
            const int rowBase = (b * H_ + rn) * W_ * C_;
            pre0 = *(const float4*)(x + rowBase + colOff0);
            if (has1) pre1 = *(const float4*)(x + rowBase + colOff1);
        }

        // sliding window: x[r, qOut-3 .. qOut+4] for this channel pair
        u64 w[NQ + 6];
        #pragma unroll
        for (int d = 0; d < NQ + 6; ++d)
            w[d] = *(const u64*)&sbuf[bi][ty * NQ + d][2 * tx];

        // 98 packed FMAs: acc[m] (output row r-3+m) uses kernel row i=m,
        // out[p,q] += k[m,j] * x[r, q+3-j]  ->  w[nq + 6 - j]
        #pragma unroll
        for (int m = 0; m < 7; ++m) {
            #pragma unroll
            for (int j = 0; j < 7; ++j) {
                const u64 kv = kreg[m * KS + j];
                fma2(acc[m][0], kv, w[6 - j]);
                fma2(acc[m][1], kv, w[7 - j]);
            }
        }

        // output row p = r-3 is complete
        const int p = r - 3;
        if (p >= p0) {
            const int base = ((b * H_ + p) * W_ + qOut) * C_ + c0;
            *(u64*)(out + base)      = acc[0][0];
            *(u64*)(out + base + C_) = acc[0][1];
        }

        // shift the ring
        #pragma unroll
        for (int m = 0; m < 6; ++m) { acc[m][0] = acc[m + 1][0]; acc[m][1] = acc[m + 1][1]; }
        acc[6][0] = 0ULL; acc[6][1] = 0ULL;

        // commit prefetched row to the other buffer
        if (doPre) {
            *(float4*)&sbuf[bi ^ 1][s0][v0 * 4] = pre0;
            if (has1) *(float4*)&sbuf[bi ^ 1][s1][v1 * 4] = pre1;
        }
        __syncthreads();
    }
}

extern "C" void kernel_launch(void* const* d_in, const int* in_sizes, int n_in,
                              void* d_out, int out_size) {
    const float* x    = (const float*)d_in[0];   // (8,224,224,192) fp32
    const float* kern = (const float*)d_in[1];   // (192,7,7) fp32
    float* out        = (float*)d_out;           // (8,224,224,192) fp32

    dim3 grid(W_ / QT, H_ / RH, B_ * 3);  // 14 x 4 x 24 = 1344 blocks
    dim3 block(PAIRS, QTH, 1);            // 256 threads
    dwconv_circ_kernel<<<grid, block>>>(x, kern, out);
}

// round 2
// speedup vs baseline: 2.1932x; 2.1932x over previous
#include <cuda_runtime.h>

#define B_  8
#define H_  224
#define W_  224
#define C_  192
#define QT  16       // q positions per block
#define NQ  2        // q per thread
#define RH  56       // output rows per block
#define PAIRS 32     // channel pairs (threadIdx.x)
#define QTH  8       // q-thread groups (threadIdx.y)
#define NTHREADS 256
#define ROWSZ (W_ * C_)
#define IMGSZ (H_ * W_ * C_)

typedef unsigned long long u64;

__device__ __forceinline__ void fma2(u64 &d, u64 a, u64 b) {
    asm("fma.rn.f32x2 %0, %1, %2, %0;" : "+l"(d) : "l"(a), "l"(b));
}
__device__ __forceinline__ u64 pack2(float lo, float hi) {
    return (u64)__float_as_uint(lo) | ((u64)__float_as_uint(hi) << 32);
}
__device__ __forceinline__ u64 ldg2(const float* p) {
    u64 v;
    asm("ld.global.nc.b64 %0, [%1];" : "=l"(v) : "l"(p));
    return v;
}

__global__ void __launch_bounds__(NTHREADS, 1)
dwconv_direct(const float* __restrict__ x, const float* __restrict__ kern,
              float* __restrict__ out)
{
    const int tx = threadIdx.x;            // channel pair 0..31
    const int ty = threadIdx.y;            // q group 0..7
    const int wt = blockIdx.x;             // 0..13
    const int ht = blockIdx.y;             // 0..3
    const int bz = blockIdx.z;             // 0..23
    const int b  = bz / 3;
    const int g  = bz % 3;

    const int qOut = wt * QT + ty * NQ;
    const int p0   = ht * RH;
    const int c0   = g * 64 + 2 * tx;

    // ---- 49 kernel taps for this channel pair -> registers (f32x2) ----
    u64 kreg[49];
    #pragma unroll
    for (int t = 0; t < 49; ++t)
        kreg[t] = pack2(kern[c0 * 49 + t], kern[(c0 + 1) * 49 + t]);

    // ---- per-thread column offsets for the 8-wide sliding window ----
    int qcol[8];
    #pragma unroll
    for (int d = 0; d < 8; ++d) {
        int q = qOut + d - 3;
        q += (q < 0) ? W_ : 0;
        q -= (q >= W_) ? W_ : 0;
        qcol[d] = q * C_ + c0;
    }

    const float* xb = x + b * IMGSZ;

    // prefetch-row cursor (circular over H)
    int rpre = p0 - 3;
    if (rpre < 0) rpre += H_;
    int rpreOff = rpre * ROWSZ;

    // 3-buffer register window pipeline: 2 rows of prefetch depth
    u64 w0[8], w1[8], w2[8];
    #pragma unroll
    for (int d = 0; d < 8; ++d) w0[d] = ldg2(xb + rpreOff + qcol[d]);
    rpre++; rpreOff += ROWSZ; if (rpre == H_) { rpre = 0; rpreOff = 0; }
    #pragma unroll
    for (int d = 0; d < 8; ++d) w1[d] = ldg2(xb + rpreOff + qcol[d]);
    rpre++; rpreOff += ROWSZ; if (rpre == H_) { rpre = 0; rpreOff = 0; }

    // rolling ring: acc[m] holds partial output row p = (cur row) - 3 + m
    u64 acc[7][NQ];
    #pragma unroll
    for (int m = 0; m < 7; ++m) { acc[m][0] = 0ULL; acc[m][1] = 0ULL; }

    // output offset for iteration it stores row p = p0 - 6 + it (guarded)
    int outOff = ((b * H_ + (p0 - 6)) * W_ + qOut) * C_ + c0;
    int it = 0;

    auto step = [&](u64 (&wc)[8], u64 (&wn)[8]) {
        // prefetch row it+2 into wn (2-deep: ~2 iterations of slack vs DRAM 577cyc)
        #pragma unroll
        for (int d = 0; d < 8; ++d) wn[d] = ldg2(xb + rpreOff + qcol[d]);
        rpre++; rpreOff += ROWSZ;
        if (rpre == H_) { rpre = 0; rpreOff = 0; }

        // 98 packed FMAs: input row rv = p0-3+it feeds 7 pending output rows
        #pragma unroll
        for (int m = 0; m < 7; ++m) {
            #pragma unroll
            for (int j = 0; j < 7; ++j) {
                const u64 kv = kreg[m * 7 + j];
                fma2(acc[m][0], kv, wc[6 - j]);
                fma2(acc[m][1], kv, wc[7 - j]);
            }
        }

        // output row p = p0-6+it complete in acc[0]
        if (it >= 6 && it < 62) {
            *(u64*)(out + outOff)      = acc[0][0];
            *(u64*)(out + outOff + C_) = acc[0][1];
        }
        outOff += ROWSZ;

        // shift ring
        #pragma unroll
        for (int m = 0; m < 6; ++m) { acc[m][0] = acc[m + 1][0]; acc[m][1] = acc[m + 1][1]; }
        acc[6][0] = 0ULL; acc[6][1] = 0ULL;
        ++it;
    };

    // 63 iterations = 21 x 3 (it=62 is a throwaway pad; loads stay in-bounds via wrap)
    #pragma unroll 1
    for (int blk = 0; blk < 21; ++blk) {
        step(w0, w2);
        step(w1, w0);
        step(w2, w1);
    }
}

extern "C" void kernel_launch(void* const* d_in, const int* in_sizes, int n_in,
                              void* d_out, int out_size) {
    const float* x    = (const float*)d_in[0];   // (8,224,224,192) fp32
    const float* kern = (const float*)d_in[1];   // (192,7,7) fp32
    float* out        = (float*)d_out;           // (8,224,224,192) fp32

    dim3 grid(W_ / QT, H_ / RH, B_ * 3);  // 14 x 4 x 24 = 1344 blocks
    dim3 block(PAIRS, QTH, 1);            // 256 threads
    dwconv_direct<<<grid, block>>>(x, kern, out);
}

// round 3
// speedup vs baseline: 2.2418x; 1.0222x over previous
#include <cuda_runtime.h>

#define B_  8
#define H_  224
#define W_  224
#define C_  192
#define QT  16       // q positions per block
#define NQ  2        // q per thread
#define RH  56       // output rows per block
#define PAIRS 32     // channel pairs (threadIdx.x)
#define QTH  8       // q-thread groups (threadIdx.y)
#define NTHREADS 256
#define ROWSZ (W_ * C_)
#define IMGSZ (H_ * W_ * C_)

typedef unsigned long long u64;

__device__ __forceinline__ void fma2(u64 &d, u64 a, u64 b) {
    asm("fma.rn.f32x2 %0, %1, %2, %0;" : "+l"(d) : "l"(a), "l"(b));
}
__device__ __forceinline__ u64 pack2(float lo, float hi) {
    return (u64)__float_as_uint(lo) | ((u64)__float_as_uint(hi) << 32);
}
__device__ __forceinline__ u64 ldg2(const float* p) {
    u64 v;
    asm("ld.global.nc.b64 %0, [%1];" : "=l"(v) : "l"(p));
    return v;
}

// One pipeline step at global step index t (input row r = p0-3+t):
//  - prefetch row t+2 into WN
//  - 98 packed FMAs from WC into static acc slots (T7 = t % 7, compile-time)
//  - output row p = p0-6+t completes in slot (T7+2)%7: store (main) / discard, then zero
#define STEP(WC, WN, T7, DOSTORE) do {                                        \
    _Pragma("unroll")                                                         \
    for (int d = 0; d < 8; ++d) WN[d] = ldg2(rowPtr + qcol[d]);               \
    rowPtr += ROWSZ; ++rpre;                                                  \
    if (rpre == H_) { rpre = 0; rowPtr -= IMGSZ; }                            \
    _Pragma("unroll")                                                         \
    for (int i = 0; i < 7; ++i) {                                             \
        const int s = ((T7) + i + 2) % 7;                                     \
        _Pragma("unroll")                                                     \
        for (int j = 0; j < 7; ++j) {                                         \
            const u64 kv = kreg[i * 7 + j];                                   \
            fma2(acc[s][0], kv, WC[6 - j]);                                   \
            fma2(acc[s][1], kv, WC[7 - j]);                                   \
        }                                                                     \
    }                                                                         \
    {                                                                         \
        const int so = ((T7) + 2) % 7;                                        \
        if (DOSTORE) {                                                        \
            *(u64*)(out + outOff)      = acc[so][0];                          \
            *(u64*)(out + outOff + C_) = acc[so][1];                          \
            outOff += ROWSZ;                                                  \
        }                                                                     \
        acc[so][0] = 0ULL; acc[so][1] = 0ULL;                                 \
    }                                                                         \
} while (0)

__global__ void __launch_bounds__(NTHREADS, 1)
dwconv_direct(const float* __restrict__ x, const float* __restrict__ kern,
              float* __restrict__ out)
{
    const int tx = threadIdx.x;            // channel pair 0..31
    const int ty = threadIdx.y;            // q group 0..7
    const int wt = blockIdx.x;             // 0..13
    const int ht = blockIdx.y;             // 0..3
    const int bz = blockIdx.z;             // 0..23
    const int b  = bz / 3;
    const int g  = bz % 3;

    const int qOut = wt * QT + ty * NQ;
    const int p0   = ht * RH;              // p0 % 7 == 0 (RH = 56)
    const int c0   = g * 64 + 2 * tx;

    // ---- 49 kernel taps for this channel pair -> registers (f32x2) ----
    u64 kreg[49];
    #pragma unroll
    for (int t = 0; t < 49; ++t)
        kreg[t] = pack2(kern[c0 * 49 + t], kern[(c0 + 1) * 49 + t]);

    // ---- per-thread column offsets for the 8-wide sliding window ----
    int qcol[8];
    #pragma unroll
    for (int d = 0; d < 8; ++d) {
        int q = qOut + d - 3;
        q += (q < 0) ? W_ : 0;
        q -= (q >= W_) ? W_ : 0;
        qcol[d] = q * C_ + c0;
    }

    // row cursor (circular over H)
    int rpre = p0 - 3;
    if (rpre < 0) rpre += H_;
    const float* rowPtr = x + b * IMGSZ + rpre * ROWSZ;

    // 4 register window buffers, 2-row prefetch depth
    u64 wA[8], wB[8], wC[8], wD[8];
    #pragma unroll
    for (int d = 0; d < 8; ++d) wA[d] = ldg2(rowPtr + qcol[d]);   // row for t=0
    rowPtr += ROWSZ; ++rpre; if (rpre == H_) { rpre = 0; rowPtr -= IMGSZ; }
    #pragma unroll
    for (int d = 0; d < 8; ++d) wB[d] = ldg2(rowPtr + qcol[d]);   // row for t=1
    rowPtr += ROWSZ; ++rpre; if (rpre == H_) { rpre = 0; rowPtr -= IMGSZ; }

    // 7 rolling accumulators (static slots), f32x2 x NQ
    u64 acc[7][2];
    #pragma unroll
    for (int m = 0; m < 7; ++m) { acc[m][0] = 0ULL; acc[m][1] = 0ULL; }

    int outOff = ((b * H_ + p0) * W_ + qOut) * C_ + c0;

    // ---- warm-up: t = 0..5 (no stores) ----
    STEP(wA, wC, 0, 0);
    STEP(wB, wD, 1, 0);
    STEP(wC, wA, 2, 0);
    STEP(wD, wB, 3, 0);
    STEP(wA, wC, 4, 0);
    STEP(wB, wD, 5, 0);

    // ---- main: t = 6..61, two fully-unrolled blocks of 28 (lcm(4,7)) ----
    #pragma unroll 1
    for (int o = 0; o < 2; ++o) {
        STEP(wC, wA, 6, 1);  STEP(wD, wB, 0, 1);  STEP(wA, wC, 1, 1);  STEP(wB, wD, 2, 1);
        STEP(wC, wA, 3, 1);  STEP(wD, wB, 4, 1);  STEP(wA, wC, 5, 1);  STEP(wB, wD, 6, 1);
        STEP(wC, wA, 0, 1);  STEP(wD, wB, 1, 1);  STEP(wA, wC, 2, 1);  STEP(wB, wD, 3, 1);
        STEP(wC, wA, 4, 1);  STEP(wD, wB, 5, 1);  STEP(wA, wC, 6, 1);  STEP(wB, wD, 0, 1);
        STEP(wC, wA, 1, 1);  STEP(wD, wB, 2, 1);  STEP(wA, wC, 3, 1);  STEP(wB, wD, 4, 1);
        STEP(wC, wA, 5, 1);  STEP(wD, wB, 6, 1);  STEP(wA, wC, 0, 1);  STEP(wB, wD, 1, 1);
        STEP(wC, wA, 2, 1);  STEP(wD, wB, 3, 1);  STEP(wA, wC, 4, 1);  STEP(wB, wD, 5, 1);
    }
}

extern "C" void kernel_launch(void* const* d_in, const int* in_sizes, int n_in,
                              void* d_out, int out_size) {
    const float* x    = (const float*)d_in[0];   // (8,224,224,192) fp32
    const float* kern = (const float*)d_in[1];   // (192,7,7) fp32
    float* out        = (float*)d_out;           // (8,224,224,192) fp32

    dim3 grid(W_ / QT, H_ / RH, B_ * 3);  // 14 x 4 x 24 = 1344 blocks
    dim3 block(PAIRS, QTH, 1);            // 256 threads
    dwconv_direct<<<grid, block>>>(x, kern, out);
}